// round 1
// baseline (speedup 1.0000x reference)
#include <cuda_runtime.h>

// Problem constants
#define B_   8192
#define T_   137
#define D_   384
#define K_   128

#define TB   256      // threads per block
#define BM   128      // rows per CTA
#define DK   16       // K-chunk (along D)
#define NCH  (D_/DK)  // 24 chunks

// Shared memory layout (floats):
//   As[2][DK][A_STRIDE]  : f tile, duplicated pairs, col = 2*row + 2*(row>>3)
//   Bs[2][DK][B_STRIDE]  : W1 tile transposed to kd-major, col = k index
#define A_STRIDE 286
#define B_STRIDE 136
#define A_BUF    (DK * A_STRIDE)   // 4576 floats
#define B_BUF    (DK * B_STRIDE)   // 2176 floats
#define SMEM_FLOATS (2*A_BUF + 2*B_BUF)   // 13504 floats = 54016 bytes

__device__ __forceinline__ void ffma2(unsigned long long& d,
                                      unsigned long long a,
                                      unsigned long long b) {
    asm("fma.rn.f32x2 %0, %1, %2, %0;" : "+l"(d) : "l"(a), "l"(b));
}

__device__ __forceinline__ float2 ull_as_f2(unsigned long long v) {
    float2 r;
    asm("mov.b64 {%0, %1}, %2;" : "=f"(r.x), "=f"(r.y) : "l"(v));
    return r;
}

__global__ void __launch_bounds__(TB, 2)
fused_heads_kernel(const float* __restrict__ f,
                   const float* __restrict__ W1,
                   const float* __restrict__ b1,
                   const float* __restrict__ gamma,
                   const float* __restrict__ beta,
                   const float* __restrict__ rmean,
                   const float* __restrict__ rvar,
                   const float* __restrict__ W2,
                   const float* __restrict__ b2,
                   float* __restrict__ out)
{
    extern __shared__ float sm[];
    float* As = sm;              // [2][DK][A_STRIDE]
    float* Bs = sm + 2 * A_BUF;  // [2][DK][B_STRIDE]

    const int tid = threadIdx.x;
    const int tx  = tid & 15;    // 16 column-thread groups
    const int ty  = tid >> 4;    // 16 row-thread groups (8 rows each)
    const int b0  = blockIdx.x * BM;
    const int t   = blockIdx.y;

    const float* fblk = f  + (size_t)b0 * D_;
    const float* w1t  = W1 + (size_t)t * (K_ * D_);

    // Global-load mapping: per chunk each thread loads 2 float4 of A and B.
    const int grp  = tid & 3;    // float4 group within 16-col chunk
    const int rowL = tid >> 2;   // 0..63

    // Accumulators: rows ty*8+i, column pairs (2*tx + 32*u, +1)
    unsigned long long acc[8][4];
    #pragma unroll
    for (int i = 0; i < 8; i++)
        #pragma unroll
        for (int u = 0; u < 4; u++) acc[i][u] = 0ull;

    float4 ra[2], rb[2];

    // ---- prologue: load + store chunk 0 into buffer 0 ----
    #pragma unroll
    for (int p = 0; p < 2; p++) {
        const int row = rowL + 64 * p;
        ra[p] = *(const float4*)(fblk + (size_t)row * D_ + grp * 4);
        rb[p] = *(const float4*)(w1t  + (size_t)row * D_ + grp * 4);
    }
    {
        float* Ab = As;  // buf 0
        float* Bb = Bs;
        #pragma unroll
        for (int p = 0; p < 2; p++) {
            const int row  = rowL + 64 * p;
            const int abase = 2 * row + 2 * (row >> 3);
            const float va[4] = {ra[p].x, ra[p].y, ra[p].z, ra[p].w};
            const float vb[4] = {rb[p].x, rb[p].y, rb[p].z, rb[p].w};
            #pragma unroll
            for (int j = 0; j < 4; j++) {
                const int kd = grp * 4 + j;
                float2 vv; vv.x = va[j]; vv.y = va[j];
                *(float2*)(Ab + kd * A_STRIDE + abase) = vv;
                Bb[kd * B_STRIDE + row] = vb[j];
            }
        }
    }
    __syncthreads();

    // ---- main loop over D chunks, double buffered ----
    for (int c = 0; c < NCH; ++c) {
        const int cur = c & 1;

        if (c + 1 < NCH) {
            const int d0 = (c + 1) * DK;
            #pragma unroll
            for (int p = 0; p < 2; p++) {
                const int row = rowL + 64 * p;
                ra[p] = *(const float4*)(fblk + (size_t)row * D_ + d0 + grp * 4);
                rb[p] = *(const float4*)(w1t  + (size_t)row * D_ + d0 + grp * 4);
            }
        }

        const float* Ab = As + cur * A_BUF + 18 * ty;   // row-group base
        const float* Bb = Bs + cur * B_BUF + 2 * tx;    // col base

        #pragma unroll
        for (int kd = 0; kd < DK; ++kd) {
            unsigned long long a2[8], bv[4];
            #pragma unroll
            for (int i = 0; i < 8; i++)
                a2[i] = *(const unsigned long long*)(Ab + kd * A_STRIDE + 2 * i);
            #pragma unroll
            for (int u = 0; u < 4; u++)
                bv[u] = *(const unsigned long long*)(Bb + kd * B_STRIDE + 32 * u);
            #pragma unroll
            for (int i = 0; i < 8; i++)
                #pragma unroll
                for (int u = 0; u < 4; u++)
                    ffma2(acc[i][u], a2[i], bv[u]);
        }

        if (c + 1 < NCH) {
            float* Aw = As + (cur ^ 1) * A_BUF;
            float* Bw = Bs + (cur ^ 1) * B_BUF;
            #pragma unroll
            for (int p = 0; p < 2; p++) {
                const int row  = rowL + 64 * p;
                const int abase = 2 * row + 2 * (row >> 3);
                const float va[4] = {ra[p].x, ra[p].y, ra[p].z, ra[p].w};
                const float vb[4] = {rb[p].x, rb[p].y, rb[p].z, rb[p].w};
                #pragma unroll
                for (int j = 0; j < 4; j++) {
                    const int kd = grp * 4 + j;
                    float2 vv; vv.x = va[j]; vv.y = va[j];
                    *(float2*)(Aw + kd * A_STRIDE + abase) = vv;
                    Bw[kd * B_STRIDE + row] = vb[j];
                }
            }
            __syncthreads();
        }
    }

    // ---- epilogue: BN(eval) + LeakyReLU + dot with W2, reduce over k ----
    float partial[8];
    #pragma unroll
    for (int i = 0; i < 8; i++) partial[i] = 0.0f;

    const int tk = t * K_;
    #pragma unroll
    for (int u = 0; u < 4; u++) {
        #pragma unroll
        for (int e = 0; e < 2; e++) {
            const int k = 2 * tx + 32 * u + e;
            const float sc = gamma[tk + k] * rsqrtf(rvar[tk + k] + 1e-5f);
            const float cc = (b1[tk + k] - rmean[tk + k]) * sc + beta[tk + k];
            const float w  = W2[tk + k];
            #pragma unroll
            for (int i = 0; i < 8; i++) {
                const float2 v = ull_as_f2(acc[i][u]);
                const float x = e ? v.y : v.x;
                float y = fmaf(x, sc, cc);
                y = fmaxf(y, 0.01f * y);     // LeakyReLU (slope 0.01)
                partial[i] = fmaf(y, w, partial[i]);
            }
        }
    }

    // reduce across the 16 column-threads (lane bits 0..3 within each half-warp)
    #pragma unroll
    for (int i = 0; i < 8; i++) {
        float s = partial[i];
        s += __shfl_xor_sync(0xffffffffu, s, 8);
        s += __shfl_xor_sync(0xffffffffu, s, 4);
        s += __shfl_xor_sync(0xffffffffu, s, 2);
        s += __shfl_xor_sync(0xffffffffu, s, 1);
        partial[i] = s;
    }

    if (tx == 0) {
        const float bias = b2[t];
        #pragma unroll
        for (int i = 0; i < 8; i++)
            out[(size_t)(b0 + ty * 8 + i) * T_ + t] = partial[i] + bias;
    }
}

extern "C" void kernel_launch(void* const* d_in, const int* in_sizes, int n_in,
                              void* d_out, int out_size)
{
    const float* f     = (const float*)d_in[0];
    const float* W1    = (const float*)d_in[1];
    const float* b1    = (const float*)d_in[2];
    const float* gamma = (const float*)d_in[3];
    const float* beta  = (const float*)d_in[4];
    const float* rmean = (const float*)d_in[5];
    const float* rvar  = (const float*)d_in[6];
    const float* W2    = (const float*)d_in[7];
    const float* b2    = (const float*)d_in[8];
    float* out = (float*)d_out;

    const int smem_bytes = SMEM_FLOATS * (int)sizeof(float);  // 54016
    cudaFuncSetAttribute(fused_heads_kernel,
                         cudaFuncAttributeMaxDynamicSharedMemorySize, smem_bytes);

    dim3 grid(B_ / BM, T_);
    fused_heads_kernel<<<grid, TB, smem_bytes>>>(f, W1, b1, gamma, beta,
                                                 rmean, rvar, W2, b2, out);
}

// round 3
// speedup vs baseline: 3.0671x; 3.0671x over previous
#include <cuda_runtime.h>
#include <cuda_bf16.h>
#include <cstdint>

// ----------------------------------------------------------------------------
// Problem constants
// ----------------------------------------------------------------------------
#define B_   8192
#define T_   137
#define D_   384
#define K_   128
#define BM   128
#define NF   (B_*D_)
#define NW   (T_*K_*D_)

#define DCHUNK 64
#define NCH    (D_/DCHUNK)        // 6
#define STAGES 3

#define TILE_BYTES  16384         // 128 rows x 128B (64 bf16)
#define STAGE_BYTES (4*TILE_BYTES)
#define OFF_CONST   (STAGES*STAGE_BYTES)          // sc[128], cc[128], w2[128]
#define OFF_RED     (OFF_CONST + 3*128*4)         // red[128][4] floats
#define SMEM_TOTAL  (OFF_RED + 128*4*4)           // 198,656 B

// ----------------------------------------------------------------------------
// bf16 hi/lo scratch (device globals; no allocation allowed)
// ----------------------------------------------------------------------------
__device__ __align__(16) __nv_bfloat16 g_f_hi[NF];
__device__ __align__(16) __nv_bfloat16 g_f_lo[NF];
__device__ __align__(16) __nv_bfloat16 g_w_hi[NW];
__device__ __align__(16) __nv_bfloat16 g_w_lo[NW];

// ----------------------------------------------------------------------------
// helpers
// ----------------------------------------------------------------------------
__device__ __forceinline__ uint32_t smem_u32(const void* p) {
    uint32_t a;
    asm("{ .reg .u64 t; cvta.to.shared.u64 t, %1; cvt.u32.u64 %0, t; }"
        : "=r"(a) : "l"(p));
    return a;
}
__device__ __forceinline__ void cp16(uint32_t saddr, const void* g) {
    asm volatile("cp.async.cg.shared.global [%0], [%1], 16;"
                 :: "r"(saddr), "l"(g) : "memory");
}
template <int N>
__device__ __forceinline__ void cp_wait() {
    asm volatile("cp.async.wait_group %0;" :: "n"(N) : "memory");
}
__device__ __forceinline__ void cp_commit() {
    asm volatile("cp.async.commit_group;" ::: "memory");
}
__device__ __forceinline__ void ldsm4(uint32_t* r, uint32_t addr) {
    asm volatile("ldmatrix.sync.aligned.m8n8.x4.shared.b16 {%0,%1,%2,%3}, [%4];"
                 : "=r"(r[0]), "=r"(r[1]), "=r"(r[2]), "=r"(r[3]) : "r"(addr));
}
__device__ __forceinline__ void mma_bf16(float* c, const uint32_t* a,
                                         const uint32_t b0, const uint32_t b1) {
    asm volatile(
        "mma.sync.aligned.m16n8k16.row.col.f32.bf16.bf16.f32 "
        "{%0,%1,%2,%3}, {%4,%5,%6,%7}, {%8,%9}, {%0,%1,%2,%3};"
        : "+f"(c[0]), "+f"(c[1]), "+f"(c[2]), "+f"(c[3])
        : "r"(a[0]), "r"(a[1]), "r"(a[2]), "r"(a[3]), "r"(b0), "r"(b1));
}
__device__ __forceinline__ uint32_t swz128(uint32_t o) {
    return o ^ ((o >> 3) & 0x70);
}

// ----------------------------------------------------------------------------
// Pre-pass: split fp32 -> bf16 (hi, lo)
// ----------------------------------------------------------------------------
__global__ void __launch_bounds__(256)
split_kernel(const float* __restrict__ f, const float* __restrict__ w1)
{
    const size_t NF4 = NF / 4, NT = NF4 + NW / 4;
    size_t i = (size_t)blockIdx.x * blockDim.x + threadIdx.x;
    if (i >= NT) return;

    float4 v;
    uint2 *dhi, *dlo;
    if (i < NF4) {
        v = ((const float4*)f)[i];
        dhi = (uint2*)g_f_hi + i;  dlo = (uint2*)g_f_lo + i;
    } else {
        size_t j = i - NF4;
        v = ((const float4*)w1)[j];
        dhi = (uint2*)g_w_hi + j;  dlo = (uint2*)g_w_lo + j;
    }
    const float x[4] = {v.x, v.y, v.z, v.w};
    __nv_bfloat16 h[4], l[4];
#pragma unroll
    for (int j = 0; j < 4; j++) {
        h[j] = __float2bfloat16_rn(x[j]);
        l[j] = __float2bfloat16_rn(x[j] - __bfloat162float(h[j]));
    }
    __nv_bfloat162 h01 = __halves2bfloat162(h[0], h[1]);
    __nv_bfloat162 h23 = __halves2bfloat162(h[2], h[3]);
    __nv_bfloat162 l01 = __halves2bfloat162(l[0], l[1]);
    __nv_bfloat162 l23 = __halves2bfloat162(l[2], l[3]);
    uint2 uh, ul;
    uh.x = *reinterpret_cast<uint32_t*>(&h01);
    uh.y = *reinterpret_cast<uint32_t*>(&h23);
    ul.x = *reinterpret_cast<uint32_t*>(&l01);
    ul.y = *reinterpret_cast<uint32_t*>(&l23);
    *dhi = uh;
    *dlo = ul;
}

// ----------------------------------------------------------------------------
// Main kernel: 128x128x384 GEMM (bf16 split, mma.sync) + BN + LReLU + dot(W2)
// ----------------------------------------------------------------------------
__global__ void __launch_bounds__(256, 1)
heads_mma_kernel(const float* __restrict__ b1,
                 const float* __restrict__ gamma,
                 const float* __restrict__ beta,
                 const float* __restrict__ rmean,
                 const float* __restrict__ rvar,
                 const float* __restrict__ W2,
                 const float* __restrict__ b2,
                 float* __restrict__ out)
{
    extern __shared__ char sm[];
    const uint32_t smem_base = smem_u32(sm);

    const int tid  = threadIdx.x;
    const int warp = tid >> 5;
    const int lane = tid & 31;
    const int wm   = warp & 1;       // M group (2 x 64 rows)
    const int wn   = warp >> 1;      // N group (4 x 32 cols)

    const int b0 = blockIdx.x * BM;
    const int t  = blockIdx.y;

    float* sc_s = (float*)(sm + OFF_CONST);
    float* cc_s = sc_s + 128;
    float* w2_s = sc_s + 256;
    float* red  = (float*)(sm + OFF_RED);     // [128][4]

    if (tid < 128) {
        const int k = t * K_ + tid;
        const float sc = gamma[k] * rsqrtf(rvar[k] + 1e-5f);
        sc_s[tid] = sc;
        cc_s[tid] = (b1[k] - rmean[k]) * sc + beta[k];
        w2_s[tid] = W2[k];
    }

    // global tile sources: [Ah, Al, Bh, Bl], row-major D_=384 cols
    const __nv_bfloat16* src[4];
    src[0] = g_f_hi + (size_t)b0 * D_;
    src[1] = g_f_lo + (size_t)b0 * D_;
    src[2] = g_w_hi + (size_t)t * (K_ * D_);
    src[3] = g_w_lo + (size_t)t * (K_ * D_);

    // per-thread cp.async mapping: 4 x 16B chunks per tile
    uint32_t sofs[4];
    int      gofs[4];
#pragma unroll
    for (int q = 0; q < 4; q++) {
        const int idx = q * 256 + tid;
        const int row = idx >> 3;
        const int seg = idx & 7;
        sofs[q] = swz128((uint32_t)(row * 128 + seg * 16));
        gofs[q] = row * D_ + seg * 8;
    }

#define ISSUE(c) do {                                                         \
    const uint32_t _sb = smem_base + ((c) % STAGES) * STAGE_BYTES;            \
    _Pragma("unroll")                                                         \
    for (int tl = 0; tl < 4; tl++) {                                          \
        _Pragma("unroll")                                                     \
        for (int q = 0; q < 4; q++)                                           \
            cp16(_sb + tl * TILE_BYTES + sofs[q], src[tl] + gofs[q] + (c) * DCHUNK); \
    }                                                                         \
    cp_commit();                                                              \
} while (0)

    // prologue: fill 3 stages
    ISSUE(0); ISSUE(1); ISSUE(2);

    // ldmatrix address pre-computation
    const int grp = lane >> 3;        // 0..3 address group
    const int lr  = lane & 7;
    const uint32_t xorv = (uint32_t)(lr << 4);
    const uint32_t aHi  = (uint32_t)((grp >> 1) * 16);
    const uint32_t bHi  = (uint32_t)((grp & 1) * 16);
    uint32_t colA[4], colB[4];
#pragma unroll
    for (int ks = 0; ks < 4; ks++) {
        colA[ks] = ((uint32_t)(ks * 32) + aHi) ^ xorv;
        colB[ks] = ((uint32_t)(ks * 32) + bHi) ^ xorv;
    }
    const uint32_t aRow = (uint32_t)((wm * 64 + (grp & 1) * 8 + lr) * 128);
    const uint32_t bRow = (uint32_t)((wn * 32 + (grp >> 1) * 8 + lr) * 128);

    float acc[4][4][4];
#pragma unroll
    for (int mi = 0; mi < 4; mi++)
#pragma unroll
        for (int ni = 0; ni < 4; ni++)
#pragma unroll
            for (int r = 0; r < 4; r++) acc[mi][ni][r] = 0.0f;

    for (int c = 0; c < NCH; ++c) {
        if (c <= 3)      cp_wait<2>();
        else if (c == 4) cp_wait<1>();
        else             cp_wait<0>();
        __syncthreads();

        const uint32_t st  = smem_base + (c % STAGES) * STAGE_BYTES;
        const uint32_t ahB = st + aRow;
        const uint32_t alB = st + TILE_BYTES + aRow;
        const uint32_t bhB = st + 2 * TILE_BYTES + bRow;
        const uint32_t blB = st + 3 * TILE_BYTES + bRow;

#pragma unroll
        for (int ks = 0; ks < 4; ks++) {
            uint32_t ah[4][4], al[4][4], bh[2][4], bl[2][4];
#pragma unroll
            for (int mi = 0; mi < 4; mi++) {
                ldsm4(ah[mi], ahB + (uint32_t)(mi * 2048) + colA[ks]);
                ldsm4(al[mi], alB + (uint32_t)(mi * 2048) + colA[ks]);
            }
#pragma unroll
            for (int nf = 0; nf < 2; nf++) {
                ldsm4(bh[nf], bhB + (uint32_t)(nf * 2048) + colB[ks]);
                ldsm4(bl[nf], blB + (uint32_t)(nf * 2048) + colB[ks]);
            }
#pragma unroll
            for (int mi = 0; mi < 4; mi++) {
#pragma unroll
                for (int ni = 0; ni < 4; ni++) {
                    const int nf = ni >> 1, p = (ni & 1) * 2;
                    mma_bf16(acc[mi][ni], ah[mi], bh[nf][p], bh[nf][p + 1]);
                    mma_bf16(acc[mi][ni], al[mi], bh[nf][p], bh[nf][p + 1]);
                    mma_bf16(acc[mi][ni], ah[mi], bl[nf][p], bl[nf][p + 1]);
                }
            }
        }

        if (c + STAGES < NCH) {
            __syncthreads();        // everyone done reading this buffer
            ISSUE(c + STAGES);
        }
    }

    // ------------------------- epilogue -------------------------
    // per-thread column constants: k = wn*32 + ni*8 + (lane&3)*2 + j
    float scr[8], ccr[8], w2r[8];
#pragma unroll
    for (int ni = 0; ni < 4; ni++)
#pragma unroll
        for (int j = 0; j < 2; j++) {
            const int k = wn * 32 + ni * 8 + (lane & 3) * 2 + j;
            scr[ni * 2 + j] = sc_s[k];
            ccr[ni * 2 + j] = cc_s[k];
            w2r[ni * 2 + j] = w2_s[k];
        }

#pragma unroll
    for (int mi = 0; mi < 4; mi++) {
#pragma unroll
        for (int h = 0; h < 2; h++) {
            float s = 0.0f;
#pragma unroll
            for (int ni = 0; ni < 4; ni++) {
#pragma unroll
                for (int j = 0; j < 2; j++) {
                    float y = fmaf(acc[mi][ni][h * 2 + j],
                                   scr[ni * 2 + j], ccr[ni * 2 + j]);
                    y = fmaxf(y, 0.01f * y);          // LeakyReLU
                    s = fmaf(y, w2r[ni * 2 + j], s);
                }
            }
            s += __shfl_xor_sync(0xffffffffu, s, 1);
            s += __shfl_xor_sync(0xffffffffu, s, 2);
            if ((lane & 3) == 0) {
                const int row = wm * 64 + mi * 16 + h * 8 + (lane >> 2);
                red[row * 4 + wn] = s;
            }
        }
    }
    __syncthreads();

    if (tid < 128) {
        const float s = red[tid * 4 + 0] + red[tid * 4 + 1]
                      + red[tid * 4 + 2] + red[tid * 4 + 3] + b2[t];
        out[(size_t)(b0 + tid) * T_ + t] = s;
    }
#undef ISSUE
}

// ----------------------------------------------------------------------------
// launch
// ----------------------------------------------------------------------------
extern "C" void kernel_launch(void* const* d_in, const int* in_sizes, int n_in,
                              void* d_out, int out_size)
{
    const float* f     = (const float*)d_in[0];
    const float* W1    = (const float*)d_in[1];
    const float* b1    = (const float*)d_in[2];
    const float* gamma = (const float*)d_in[3];
    const float* beta  = (const float*)d_in[4];
    const float* rmean = (const float*)d_in[5];
    const float* rvar  = (const float*)d_in[6];
    const float* W2    = (const float*)d_in[7];
    const float* b2    = (const float*)d_in[8];
    float* out = (float*)d_out;

    {
        const size_t total4 = (size_t)NF / 4 + (size_t)NW / 4;
        const int blocks = (int)((total4 + 255) / 256);
        split_kernel<<<blocks, 256>>>(f, W1);
    }

    cudaFuncSetAttribute(heads_mma_kernel,
                         cudaFuncAttributeMaxDynamicSharedMemorySize, SMEM_TOTAL);
    dim3 grid(B_ / BM, T_);
    heads_mma_kernel<<<grid, 256, SMEM_TOTAL>>>(b1, gamma, beta, rmean, rvar,
                                                W2, b2, out);
}

// round 4
// speedup vs baseline: 4.3345x; 1.4132x over previous
#include <cuda_runtime.h>
#include <cuda_fp16.h>
#include <cstdint>

// ----------------------------------------------------------------------------
// Problem constants
// ----------------------------------------------------------------------------
#define B_   8192
#define T_   137
#define D_   384
#define K_   128
#define BM   128
#define NF   (B_*D_)
#define NW   (T_*K_*D_)

#define DCHUNK 64
#define NCH    (D_/DCHUNK)        // 6
#define STAGES 4

#define TILE_BYTES  16384         // 128 rows x 128B (64 fp16)
#define STAGE_BYTES (3*TILE_BYTES)                 // Ah, Al, Bh
#define OFF_CONST   (STAGES*STAGE_BYTES)           // 196608
#define OFF_RED     (OFF_CONST + 3*128*4)
#define SMEM_TOTAL  (OFF_RED + 128*4*4)            // 200,192 B

// ----------------------------------------------------------------------------
// fp16 scratch (device globals; no allocation allowed)
// ----------------------------------------------------------------------------
__device__ __align__(16) __half g_f_hi[NF];
__device__ __align__(16) __half g_f_lo[NF];
__device__ __align__(16) __half g_w_h [NW];

// ----------------------------------------------------------------------------
// helpers
// ----------------------------------------------------------------------------
__device__ __forceinline__ uint32_t smem_u32(const void* p) {
    uint32_t a;
    asm("{ .reg .u64 t; cvta.to.shared.u64 t, %1; cvt.u32.u64 %0, t; }"
        : "=r"(a) : "l"(p));
    return a;
}
__device__ __forceinline__ void cp16(uint32_t saddr, const void* g) {
    asm volatile("cp.async.cg.shared.global [%0], [%1], 16;"
                 :: "r"(saddr), "l"(g) : "memory");
}
template <int N>
__device__ __forceinline__ void cp_wait() {
    asm volatile("cp.async.wait_group %0;" :: "n"(N) : "memory");
}
__device__ __forceinline__ void cp_commit() {
    asm volatile("cp.async.commit_group;" ::: "memory");
}
__device__ __forceinline__ void ldsm4(uint32_t* r, uint32_t addr) {
    asm volatile("ldmatrix.sync.aligned.m8n8.x4.shared.b16 {%0,%1,%2,%3}, [%4];"
                 : "=r"(r[0]), "=r"(r[1]), "=r"(r[2]), "=r"(r[3]) : "r"(addr));
}
__device__ __forceinline__ void mma_f16(float* c, const uint32_t* a,
                                        const uint32_t b0, const uint32_t b1) {
    asm volatile(
        "mma.sync.aligned.m16n8k16.row.col.f32.f16.f16.f32 "
        "{%0,%1,%2,%3}, {%4,%5,%6,%7}, {%8,%9}, {%0,%1,%2,%3};"
        : "+f"(c[0]), "+f"(c[1]), "+f"(c[2]), "+f"(c[3])
        : "r"(a[0]), "r"(a[1]), "r"(a[2]), "r"(a[3]), "r"(b0), "r"(b1));
}
__device__ __forceinline__ uint32_t swz128(uint32_t o) {
    return o ^ ((o >> 3) & 0x70);
}

// ----------------------------------------------------------------------------
// Pre-pass: f -> fp16 (hi, lo) split;  W1 -> fp16 round
// ----------------------------------------------------------------------------
__global__ void __launch_bounds__(256)
split_kernel(const float* __restrict__ f, const float* __restrict__ w1)
{
    const size_t NF4 = NF / 4, NT = NF4 + NW / 4;
    size_t i = (size_t)blockIdx.x * blockDim.x + threadIdx.x;
    if (i >= NT) return;

    if (i < NF4) {
        float4 v = ((const float4*)f)[i];
        const float x[4] = {v.x, v.y, v.z, v.w};
        __half h[4], l[4];
#pragma unroll
        for (int j = 0; j < 4; j++) {
            h[j] = __float2half_rn(x[j]);
            l[j] = __float2half_rn(x[j] - __half2float(h[j]));
        }
        __half2 h01 = __halves2half2(h[0], h[1]);
        __half2 h23 = __halves2half2(h[2], h[3]);
        __half2 l01 = __halves2half2(l[0], l[1]);
        __half2 l23 = __halves2half2(l[2], l[3]);
        uint2 uh, ul;
        uh.x = *reinterpret_cast<uint32_t*>(&h01);
        uh.y = *reinterpret_cast<uint32_t*>(&h23);
        ul.x = *reinterpret_cast<uint32_t*>(&l01);
        ul.y = *reinterpret_cast<uint32_t*>(&l23);
        ((uint2*)g_f_hi)[i] = uh;
        ((uint2*)g_f_lo)[i] = ul;
    } else {
        size_t j = i - NF4;
        float4 v = ((const float4*)w1)[j];
        __half2 h01 = __halves2half2(__float2half_rn(v.x), __float2half_rn(v.y));
        __half2 h23 = __halves2half2(__float2half_rn(v.z), __float2half_rn(v.w));
        uint2 uh;
        uh.x = *reinterpret_cast<uint32_t*>(&h01);
        uh.y = *reinterpret_cast<uint32_t*>(&h23);
        ((uint2*)g_w_h)[j] = uh;
    }
}

// ----------------------------------------------------------------------------
// Main kernel: 128x128x384 GEMM (fp16 2-term split) + BN + LReLU + dot(W2)
// ----------------------------------------------------------------------------
__global__ void __launch_bounds__(256, 1)
heads_mma_kernel(const float* __restrict__ b1,
                 const float* __restrict__ gamma,
                 const float* __restrict__ beta,
                 const float* __restrict__ rmean,
                 const float* __restrict__ rvar,
                 const float* __restrict__ W2,
                 const float* __restrict__ b2,
                 float* __restrict__ out)
{
    extern __shared__ char sm[];
    const uint32_t smem_base = smem_u32(sm);

    const int tid  = threadIdx.x;
    const int warp = tid >> 5;
    const int lane = tid & 31;
    const int wm   = warp & 1;       // M group (2 x 64 rows)
    const int wn   = warp >> 1;      // N group (4 x 32 cols)

    const int b0 = blockIdx.x * BM;
    const int t  = blockIdx.y;

    float* sc_s = (float*)(sm + OFF_CONST);
    float* cc_s = sc_s + 128;
    float* w2_s = sc_s + 256;
    float* red  = (float*)(sm + OFF_RED);     // [128][4]

    if (tid < 128) {
        const int k = t * K_ + tid;
        const float sc = gamma[k] * rsqrtf(rvar[k] + 1e-5f);
        sc_s[tid] = sc;
        cc_s[tid] = (b1[k] - rmean[k]) * sc + beta[k];
        w2_s[tid] = W2[k];
    }

    // global tile sources: [Ah, Al, Bh], row-major D_=384 cols
    const __half* src[3];
    src[0] = g_f_hi + (size_t)b0 * D_;
    src[1] = g_f_lo + (size_t)b0 * D_;
    src[2] = g_w_h  + (size_t)t * (K_ * D_);

    // per-thread cp.async mapping: 4 x 16B chunks per tile
    uint32_t sofs[4];
    int      gofs[4];
#pragma unroll
    for (int q = 0; q < 4; q++) {
        const int idx = q * 256 + tid;
        const int row = idx >> 3;
        const int seg = idx & 7;
        sofs[q] = swz128((uint32_t)(row * 128 + seg * 16));
        gofs[q] = row * D_ + seg * 8;
    }

#define ISSUE(c) do {                                                         \
    const uint32_t _sb = smem_base + ((c) % STAGES) * STAGE_BYTES;            \
    _Pragma("unroll")                                                         \
    for (int tl = 0; tl < 3; tl++) {                                          \
        _Pragma("unroll")                                                     \
        for (int q = 0; q < 4; q++)                                           \
            cp16(_sb + tl * TILE_BYTES + sofs[q], src[tl] + gofs[q] + (c) * DCHUNK); \
    }                                                                         \
    cp_commit();                                                              \
} while (0)

    // prologue: fill 4 stages
    ISSUE(0); ISSUE(1); ISSUE(2); ISSUE(3);

    // ldmatrix address pre-computation
    const int grp = lane >> 3;        // 0..3 address group
    const int lr  = lane & 7;
    const uint32_t xorv = (uint32_t)(lr << 4);
    const uint32_t aHi  = (uint32_t)((grp >> 1) * 16);
    const uint32_t bHi  = (uint32_t)((grp & 1) * 16);
    uint32_t colA[4], colB[4];
#pragma unroll
    for (int ks = 0; ks < 4; ks++) {
        colA[ks] = ((uint32_t)(ks * 32) + aHi) ^ xorv;
        colB[ks] = ((uint32_t)(ks * 32) + bHi) ^ xorv;
    }
    const uint32_t aRow = (uint32_t)((wm * 64 + (grp & 1) * 8 + lr) * 128);
    const uint32_t bRow = (uint32_t)((wn * 32 + (grp >> 1) * 8 + lr) * 128);

    float acc[4][4][4];
#pragma unroll
    for (int mi = 0; mi < 4; mi++)
#pragma unroll
        for (int ni = 0; ni < 4; ni++)
#pragma unroll
            for (int r = 0; r < 4; r++) acc[mi][ni][r] = 0.0f;

    for (int c = 0; c < NCH; ++c) {
        // groups issued so far: min(c+4, 6); need group c done.
        if (c <= 2)      cp_wait<3>();
        else if (c == 3) cp_wait<2>();
        else if (c == 4) cp_wait<1>();
        else             cp_wait<0>();
        __syncthreads();

        const uint32_t st  = smem_base + (c % STAGES) * STAGE_BYTES;
        const uint32_t ahB = st + aRow;
        const uint32_t alB = st + TILE_BYTES + aRow;
        const uint32_t bhB = st + 2 * TILE_BYTES + bRow;

#pragma unroll
        for (int ks = 0; ks < 4; ks++) {
            uint32_t ah[4][4], al[4][4], bh[2][4];
#pragma unroll
            for (int mi = 0; mi < 4; mi++) {
                ldsm4(ah[mi], ahB + (uint32_t)(mi * 2048) + colA[ks]);
                ldsm4(al[mi], alB + (uint32_t)(mi * 2048) + colA[ks]);
            }
#pragma unroll
            for (int nf = 0; nf < 2; nf++)
                ldsm4(bh[nf], bhB + (uint32_t)(nf * 2048) + colB[ks]);

            // term-major: all Ah*Bh first, then all Al*Bh — no RAW chains
#pragma unroll
            for (int mi = 0; mi < 4; mi++)
#pragma unroll
                for (int ni = 0; ni < 4; ni++) {
                    const int nf = ni >> 1, p = (ni & 1) * 2;
                    mma_f16(acc[mi][ni], ah[mi], bh[nf][p], bh[nf][p + 1]);
                }
#pragma unroll
            for (int mi = 0; mi < 4; mi++)
#pragma unroll
                for (int ni = 0; ni < 4; ni++) {
                    const int nf = ni >> 1, p = (ni & 1) * 2;
                    mma_f16(acc[mi][ni], al[mi], bh[nf][p], bh[nf][p + 1]);
                }
        }

        if (c + STAGES < NCH) {
            __syncthreads();        // everyone done reading this buffer
            ISSUE(c + STAGES);
        }
    }

    // ------------------------- epilogue -------------------------
    float scr[8], ccr[8], w2r[8];
#pragma unroll
    for (int ni = 0; ni < 4; ni++)
#pragma unroll
        for (int j = 0; j < 2; j++) {
            const int k = wn * 32 + ni * 8 + (lane & 3) * 2 + j;
            scr[ni * 2 + j] = sc_s[k];
            ccr[ni * 2 + j] = cc_s[k];
            w2r[ni * 2 + j] = w2_s[k];
        }

#pragma unroll
    for (int mi = 0; mi < 4; mi++) {
#pragma unroll
        for (int h = 0; h < 2; h++) {
            float s = 0.0f;
#pragma unroll
            for (int ni = 0; ni < 4; ni++) {
#pragma unroll
                for (int j = 0; j < 2; j++) {
                    float y = fmaf(acc[mi][ni][h * 2 + j],
                                   scr[ni * 2 + j], ccr[ni * 2 + j]);
                    y = fmaxf(y, 0.01f * y);          // LeakyReLU
                    s = fmaf(y, w2r[ni * 2 + j], s);
                }
            }
            s += __shfl_xor_sync(0xffffffffu, s, 1);
            s += __shfl_xor_sync(0xffffffffu, s, 2);
            if ((lane & 3) == 0) {
                const int row = wm * 64 + mi * 16 + h * 8 + (lane >> 2);
                red[row * 4 + wn] = s;
            }
        }
    }
    __syncthreads();

    if (tid < 128) {
        const float s = red[tid * 4 + 0] + red[tid * 4 + 1]
                      + red[tid * 4 + 2] + red[tid * 4 + 3] + b2[t];
        out[(size_t)(b0 + tid) * T_ + t] = s;
    }
#undef ISSUE
}

// ----------------------------------------------------------------------------
// launch
// ----------------------------------------------------------------------------
extern "C" void kernel_launch(void* const* d_in, const int* in_sizes, int n_in,
                              void* d_out, int out_size)
{
    const float* f     = (const float*)d_in[0];
    const float* W1    = (const float*)d_in[1];
    const float* b1    = (const float*)d_in[2];
    const float* gamma = (const float*)d_in[3];
    const float* beta  = (const float*)d_in[4];
    const float* rmean = (const float*)d_in[5];
    const float* rvar  = (const float*)d_in[6];
    const float* W2    = (const float*)d_in[7];
    const float* b2    = (const float*)d_in[8];
    float* out = (float*)d_out;

    {
        const size_t total4 = (size_t)NF / 4 + (size_t)NW / 4;
        const int blocks = (int)((total4 + 255) / 256);
        split_kernel<<<blocks, 256>>>(f, W1);
    }

    cudaFuncSetAttribute(heads_mma_kernel,
                         cudaFuncAttributeMaxDynamicSharedMemorySize, SMEM_TOTAL);
    dim3 grid(B_ / BM, T_);
    heads_mma_kernel<<<grid, 256, SMEM_TOTAL>>>(b1, gamma, beta, rmean, rvar,
                                                W2, b2, out);
}

// round 5
// speedup vs baseline: 8.8827x; 2.0493x over previous
#include <cuda_runtime.h>
#include <cuda_fp16.h>
#include <cstdint>

// ----------------------------------------------------------------------------
// Problem constants
// ----------------------------------------------------------------------------
#define B_   8192
#define T_   137
#define D_   384
#define K_   128
#define BM   128
#define NF   (B_*D_)
#define NW   (T_*K_*D_)

#define DCHUNK 64
#define NCH    (D_/DCHUNK)        // 6
#define STAGES 3

#define TILE_BYTES  16384         // 128 rows x 128B (64 fp16)
#define STAGE_BYTES (2*TILE_BYTES)                 // A, B
#define OFF_CONST   (STAGES*STAGE_BYTES)           // 98304
#define OFF_RED     (OFF_CONST + 3*128*4)
#define SMEM_TOTAL  (OFF_RED + 128*4*4)            // 101,888 B -> 2 CTAs/SM

// ----------------------------------------------------------------------------
// fp16 scratch (device globals; no allocation allowed)
// ----------------------------------------------------------------------------
__device__ __align__(16) __half g_f_h[NF];
__device__ __align__(16) __half g_w_h[NW];

// ----------------------------------------------------------------------------
// helpers
// ----------------------------------------------------------------------------
__device__ __forceinline__ uint32_t smem_u32(const void* p) {
    uint32_t a;
    asm("{ .reg .u64 t; cvta.to.shared.u64 t, %1; cvt.u32.u64 %0, t; }"
        : "=r"(a) : "l"(p));
    return a;
}
__device__ __forceinline__ void cp16(uint32_t saddr, const void* g) {
    asm volatile("cp.async.cg.shared.global [%0], [%1], 16;"
                 :: "r"(saddr), "l"(g) : "memory");
}
template <int N>
__device__ __forceinline__ void cp_wait() {
    asm volatile("cp.async.wait_group %0;" :: "n"(N) : "memory");
}
__device__ __forceinline__ void cp_commit() {
    asm volatile("cp.async.commit_group;" ::: "memory");
}
__device__ __forceinline__ void ldsm4(uint32_t* r, uint32_t addr) {
    asm volatile("ldmatrix.sync.aligned.m8n8.x4.shared.b16 {%0,%1,%2,%3}, [%4];"
                 : "=r"(r[0]), "=r"(r[1]), "=r"(r[2]), "=r"(r[3]) : "r"(addr));
}
__device__ __forceinline__ void mma_f16(float* c, const uint32_t* a,
                                        const uint32_t b0, const uint32_t b1) {
    asm volatile(
        "mma.sync.aligned.m16n8k16.row.col.f32.f16.f16.f32 "
        "{%0,%1,%2,%3}, {%4,%5,%6,%7}, {%8,%9}, {%0,%1,%2,%3};"
        : "+f"(c[0]), "+f"(c[1]), "+f"(c[2]), "+f"(c[3])
        : "r"(a[0]), "r"(a[1]), "r"(a[2]), "r"(a[3]), "r"(b0), "r"(b1));
}
__device__ __forceinline__ uint32_t swz128(uint32_t o) {
    return o ^ ((o >> 3) & 0x70);
}

// ----------------------------------------------------------------------------
// Pre-pass: f, W1 -> fp16 (round-to-nearest)
// ----------------------------------------------------------------------------
__global__ void __launch_bounds__(256)
split_kernel(const float* __restrict__ f, const float* __restrict__ w1)
{
    const size_t NF4 = NF / 4, NT = NF4 + NW / 4;
    size_t i = (size_t)blockIdx.x * blockDim.x + threadIdx.x;
    if (i >= NT) return;

    float4 v;
    uint2* dst;
    if (i < NF4) {
        v = ((const float4*)f)[i];
        dst = (uint2*)g_f_h + i;
    } else {
        size_t j = i - NF4;
        v = ((const float4*)w1)[j];
        dst = (uint2*)g_w_h + j;
    }
    __half2 h01 = __halves2half2(__float2half_rn(v.x), __float2half_rn(v.y));
    __half2 h23 = __halves2half2(__float2half_rn(v.z), __float2half_rn(v.w));
    uint2 u;
    u.x = *reinterpret_cast<uint32_t*>(&h01);
    u.y = *reinterpret_cast<uint32_t*>(&h23);
    *dst = u;
}

// ----------------------------------------------------------------------------
// Main kernel: 128x128x384 GEMM (fp16 single-term) + BN + LReLU + dot(W2)
// ----------------------------------------------------------------------------
__global__ void __launch_bounds__(256, 2)
heads_mma_kernel(const float* __restrict__ b1,
                 const float* __restrict__ gamma,
                 const float* __restrict__ beta,
                 const float* __restrict__ rmean,
                 const float* __restrict__ rvar,
                 const float* __restrict__ W2,
                 const float* __restrict__ b2,
                 float* __restrict__ out)
{
    extern __shared__ char sm[];
    const uint32_t smem_base = smem_u32(sm);

    const int tid  = threadIdx.x;
    const int warp = tid >> 5;
    const int lane = tid & 31;
    const int wm   = warp & 1;       // M group (2 x 64 rows)
    const int wn   = warp >> 1;      // N group (4 x 32 cols)

    const int b0 = blockIdx.x * BM;
    const int t  = blockIdx.y;

    float* sc_s = (float*)(sm + OFF_CONST);
    float* cc_s = sc_s + 128;
    float* w2_s = sc_s + 256;
    float* red  = (float*)(sm + OFF_RED);     // [128][4]

    if (tid < 128) {
        const int k = t * K_ + tid;
        const float sc = gamma[k] * rsqrtf(rvar[k] + 1e-5f);
        sc_s[tid] = sc;
        cc_s[tid] = (b1[k] - rmean[k]) * sc + beta[k];
        w2_s[tid] = W2[k];
    }

    // global tile sources: [A, B], row-major D_=384 cols
    const __half* src[2];
    src[0] = g_f_h + (size_t)b0 * D_;
    src[1] = g_w_h + (size_t)t * (K_ * D_);

    // per-thread cp.async mapping: 4 x 16B chunks per tile
    uint32_t sofs[4];
    int      gofs[4];
#pragma unroll
    for (int q = 0; q < 4; q++) {
        const int idx = q * 256 + tid;
        const int row = idx >> 3;
        const int seg = idx & 7;
        sofs[q] = swz128((uint32_t)(row * 128 + seg * 16));
        gofs[q] = row * D_ + seg * 8;
    }

#define ISSUE(c) do {                                                         \
    const uint32_t _sb = smem_base + ((c) % STAGES) * STAGE_BYTES;            \
    _Pragma("unroll")                                                         \
    for (int tl = 0; tl < 2; tl++) {                                          \
        _Pragma("unroll")                                                     \
        for (int q = 0; q < 4; q++)                                           \
            cp16(_sb + tl * TILE_BYTES + sofs[q], src[tl] + gofs[q] + (c) * DCHUNK); \
    }                                                                         \
    cp_commit();                                                              \
} while (0)

    // prologue: fill 3 stages
    ISSUE(0); ISSUE(1); ISSUE(2);

    // ldmatrix address pre-computation
    const int grp = lane >> 3;        // 0..3 address group
    const int lr  = lane & 7;
    const uint32_t xorv = (uint32_t)(lr << 4);
    const uint32_t aHi  = (uint32_t)((grp >> 1) * 16);
    const uint32_t bHi  = (uint32_t)((grp & 1) * 16);
    uint32_t colA[4], colB[4];
#pragma unroll
    for (int ks = 0; ks < 4; ks++) {
        colA[ks] = ((uint32_t)(ks * 32) + aHi) ^ xorv;
        colB[ks] = ((uint32_t)(ks * 32) + bHi) ^ xorv;
    }
    const uint32_t aRow = (uint32_t)((wm * 64 + (grp & 1) * 8 + lr) * 128);
    const uint32_t bRow = (uint32_t)((wn * 32 + (grp >> 1) * 8 + lr) * 128);

    float acc[4][4][4];
#pragma unroll
    for (int mi = 0; mi < 4; mi++)
#pragma unroll
        for (int ni = 0; ni < 4; ni++)
#pragma unroll
            for (int r = 0; r < 4; r++) acc[mi][ni][r] = 0.0f;

    for (int c = 0; c < NCH; ++c) {
        // groups committed so far: min(c+3, 6); need group c complete.
        if (c <= 3)      cp_wait<2>();
        else if (c == 4) cp_wait<1>();
        else             cp_wait<0>();
        __syncthreads();

        const uint32_t st  = smem_base + (c % STAGES) * STAGE_BYTES;
        const uint32_t aB  = st + aRow;
        const uint32_t bB  = st + TILE_BYTES + bRow;

#pragma unroll
        for (int ks = 0; ks < 4; ks++) {
            uint32_t af[4][4], bf[2][4];
#pragma unroll
            for (int mi = 0; mi < 4; mi++)
                ldsm4(af[mi], aB + (uint32_t)(mi * 2048) + colA[ks]);
#pragma unroll
            for (int nf = 0; nf < 2; nf++)
                ldsm4(bf[nf], bB + (uint32_t)(nf * 2048) + colB[ks]);

            // 16 independent accumulators — no RAW chains
#pragma unroll
            for (int mi = 0; mi < 4; mi++)
#pragma unroll
                for (int ni = 0; ni < 4; ni++) {
                    const int nf = ni >> 1, p = (ni & 1) * 2;
                    mma_f16(acc[mi][ni], af[mi], bf[nf][p], bf[nf][p + 1]);
                }
        }

        if (c + STAGES < NCH) {
            __syncthreads();        // everyone done reading this buffer
            ISSUE(c + STAGES);
        }
    }

    // ------------------------- epilogue -------------------------
    float scr[8], ccr[8], w2r[8];
#pragma unroll
    for (int ni = 0; ni < 4; ni++)
#pragma unroll
        for (int j = 0; j < 2; j++) {
            const int k = wn * 32 + ni * 8 + (lane & 3) * 2 + j;
            scr[ni * 2 + j] = sc_s[k];
            ccr[ni * 2 + j] = cc_s[k];
            w2r[ni * 2 + j] = w2_s[k];
        }

#pragma unroll
    for (int mi = 0; mi < 4; mi++) {
#pragma unroll
        for (int h = 0; h < 2; h++) {
            float s = 0.0f;
#pragma unroll
            for (int ni = 0; ni < 4; ni++) {
#pragma unroll
                for (int j = 0; j < 2; j++) {
                    float y = fmaf(acc[mi][ni][h * 2 + j],
                                   scr[ni * 2 + j], ccr[ni * 2 + j]);
                    y = fmaxf(y, 0.01f * y);          // LeakyReLU
                    s = fmaf(y, w2r[ni * 2 + j], s);
                }
            }
            s += __shfl_xor_sync(0xffffffffu, s, 1);
            s += __shfl_xor_sync(0xffffffffu, s, 2);
            if ((lane & 3) == 0) {
                const int row = wm * 64 + mi * 16 + h * 8 + (lane >> 2);
                red[row * 4 + wn] = s;
            }
        }
    }
    __syncthreads();

    if (tid < 128) {
        const float s = red[tid * 4 + 0] + red[tid * 4 + 1]
                      + red[tid * 4 + 2] + red[tid * 4 + 3] + b2[t];
        out[(size_t)(b0 + tid) * T_ + t] = s;
    }
#undef ISSUE
}

// ----------------------------------------------------------------------------
// launch
// ----------------------------------------------------------------------------
extern "C" void kernel_launch(void* const* d_in, const int* in_sizes, int n_in,
                              void* d_out, int out_size)
{
    const float* f     = (const float*)d_in[0];
    const float* W1    = (const float*)d_in[1];
    const float* b1    = (const float*)d_in[2];
    const float* gamma = (const float*)d_in[3];
    const float* beta  = (const float*)d_in[4];
    const float* rmean = (const float*)d_in[5];
    const float* rvar  = (const float*)d_in[6];
    const float* W2    = (const float*)d_in[7];
    const float* b2    = (const float*)d_in[8];
    float* out = (float*)d_out;

    {
        const size_t total4 = (size_t)NF / 4 + (size_t)NW / 4;
        const int blocks = (int)((total4 + 255) / 256);
        split_kernel<<<blocks, 256>>>(f, W1);
    }

    cudaFuncSetAttribute(heads_mma_kernel,
                         cudaFuncAttributeMaxDynamicSharedMemorySize, SMEM_TOTAL);
    dim3 grid(B_ / BM, T_);
    heads_mma_kernel<<<grid, 256, SMEM_TOTAL>>>(b1, gamma, beta, rmean, rvar,
                                                W2, b2, out);
}

// round 6
// speedup vs baseline: 9.4559x; 1.0645x over previous
#include <cuda_runtime.h>
#include <cuda_fp16.h>
#include <cstdint>

// ----------------------------------------------------------------------------
// Problem constants
// ----------------------------------------------------------------------------
#define B_   8192
#define T_   137
#define D_   384
#define K_   128
#define BM   128
#define NF   (B_*D_)
#define NW   (T_*K_*D_)

#define DCHUNK 64
#define NCH    (D_/DCHUNK)        // 6
#define STAGES 3

#define TILE_BYTES  16384         // 128 rows x 128B (64 fp16)
#define STAGE_BYTES (2*TILE_BYTES)                 // A, B
#define OFF_CONST   (STAGES*STAGE_BYTES)           // 98304
#define OFF_RED     (OFF_CONST + 3*128*4)
#define SMEM_TOTAL  (OFF_RED + 128*4*4)            // 101,888 B -> 2 CTAs/SM

// ----------------------------------------------------------------------------
// fp16 scratch (device globals; no allocation allowed)
// ----------------------------------------------------------------------------
__device__ __align__(16) __half g_f_h[NF];
__device__ __align__(16) __half g_w_h[NW];

// ----------------------------------------------------------------------------
// helpers
// ----------------------------------------------------------------------------
__device__ __forceinline__ uint32_t smem_u32(const void* p) {
    uint32_t a;
    asm("{ .reg .u64 t; cvta.to.shared.u64 t, %1; cvt.u32.u64 %0, t; }"
        : "=r"(a) : "l"(p));
    return a;
}
__device__ __forceinline__ void cp16(uint32_t saddr, const void* g) {
    asm volatile("cp.async.cg.shared.global [%0], [%1], 16;"
                 :: "r"(saddr), "l"(g) : "memory");
}
template <int N>
__device__ __forceinline__ void cp_wait() {
    asm volatile("cp.async.wait_group %0;" :: "n"(N) : "memory");
}
__device__ __forceinline__ void cp_commit() {
    asm volatile("cp.async.commit_group;" ::: "memory");
}
__device__ __forceinline__ void ldsm4(uint32_t* r, uint32_t addr) {
    asm volatile("ldmatrix.sync.aligned.m8n8.x4.shared.b16 {%0,%1,%2,%3}, [%4];"
                 : "=r"(r[0]), "=r"(r[1]), "=r"(r[2]), "=r"(r[3]) : "r"(addr));
}
__device__ __forceinline__ void mma_f16(float* c, const uint32_t* a,
                                        const uint32_t b0, const uint32_t b1) {
    asm volatile(
        "mma.sync.aligned.m16n8k16.row.col.f32.f16.f16.f32 "
        "{%0,%1,%2,%3}, {%4,%5,%6,%7}, {%8,%9}, {%0,%1,%2,%3};"
        : "+f"(c[0]), "+f"(c[1]), "+f"(c[2]), "+f"(c[3])
        : "r"(a[0]), "r"(a[1]), "r"(a[2]), "r"(a[3]), "r"(b0), "r"(b1));
}
__device__ __forceinline__ uint32_t swz128(uint32_t o) {
    return o ^ ((o >> 3) & 0x70);
}

// ----------------------------------------------------------------------------
// Pre-pass: f, W1 -> fp16 (round-to-nearest)
// ----------------------------------------------------------------------------
__global__ void __launch_bounds__(256)
split_kernel(const float* __restrict__ f, const float* __restrict__ w1)
{
    const size_t NF4 = NF / 4, NT = NF4 + NW / 4;
    size_t i = (size_t)blockIdx.x * blockDim.x + threadIdx.x;
    if (i >= NT) return;

    float4 v;
    uint2* dst;
    if (i < NF4) {
        v = ((const float4*)f)[i];
        dst = (uint2*)g_f_h + i;
    } else {
        size_t j = i - NF4;
        v = ((const float4*)w1)[j];
        dst = (uint2*)g_w_h + j;
    }
    __half2 h01 = __halves2half2(__float2half_rn(v.x), __float2half_rn(v.y));
    __half2 h23 = __halves2half2(__float2half_rn(v.z), __float2half_rn(v.w));
    uint2 u;
    u.x = *reinterpret_cast<uint32_t*>(&h01);
    u.y = *reinterpret_cast<uint32_t*>(&h23);
    *dst = u;
}

// ----------------------------------------------------------------------------
// Main kernel: 128x128x384 GEMM (fp16 single-term) + BN + LReLU + dot(W2)
// Fully unrolled 6-chunk pipeline, interleaved ldsm/MMA.
// ----------------------------------------------------------------------------
__global__ void __launch_bounds__(256, 2)
heads_mma_kernel(const float* __restrict__ b1,
                 const float* __restrict__ gamma,
                 const float* __restrict__ beta,
                 const float* __restrict__ rmean,
                 const float* __restrict__ rvar,
                 const float* __restrict__ W2,
                 const float* __restrict__ b2,
                 float* __restrict__ out)
{
    extern __shared__ char sm[];
    const uint32_t smem_base = smem_u32(sm);

    const int tid  = threadIdx.x;
    const int warp = tid >> 5;
    const int lane = tid & 31;
    const int wm   = warp & 1;       // M group (2 x 64 rows)
    const int wn   = warp >> 1;      // N group (4 x 32 cols)

    const int b0 = blockIdx.x * BM;
    const int t  = blockIdx.y;

    float* sc_s = (float*)(sm + OFF_CONST);
    float* cc_s = sc_s + 128;
    float* w2_s = sc_s + 256;
    float* red  = (float*)(sm + OFF_RED);     // [128][4]

    if (tid < 128) {
        const int k = t * K_ + tid;
        const float sc = gamma[k] * rsqrtf(rvar[k] + 1e-5f);
        sc_s[tid] = sc;
        cc_s[tid] = (b1[k] - rmean[k]) * sc + beta[k];
        w2_s[tid] = W2[k];
    }

    // global tile sources: [A, B], row-major D_=384 cols
    const __half* srcA = g_f_h + (size_t)b0 * D_;
    const __half* srcB = g_w_h + (size_t)t * (K_ * D_);

    // per-thread cp.async mapping: 4 x 16B chunks per tile
    uint32_t sofs[4];
    int      gofs[4];
#pragma unroll
    for (int q = 0; q < 4; q++) {
        const int idx = q * 256 + tid;
        const int row = idx >> 3;
        const int seg = idx & 7;
        sofs[q] = swz128((uint32_t)(row * 128 + seg * 16));
        gofs[q] = row * D_ + seg * 8;
    }

#define ISSUE(c) do {                                                        \
    const uint32_t _sb = smem_base + ((c) % STAGES) * STAGE_BYTES;           \
    _Pragma("unroll")                                                        \
    for (int q = 0; q < 4; q++)                                              \
        cp16(_sb + sofs[q], srcA + gofs[q] + (c) * DCHUNK);                  \
    _Pragma("unroll")                                                        \
    for (int q = 0; q < 4; q++)                                              \
        cp16(_sb + TILE_BYTES + sofs[q], srcB + gofs[q] + (c) * DCHUNK);     \
    cp_commit();                                                             \
} while (0)

    // prologue: fill 3 stages
    ISSUE(0); ISSUE(1); ISSUE(2);

    // ldmatrix address pre-computation
    const int grp = lane >> 3;        // 0..3 address group
    const int lr  = lane & 7;
    const uint32_t xorv = (uint32_t)(lr << 4);
    const uint32_t aHi  = (uint32_t)((grp >> 1) * 16);
    const uint32_t bHi  = (uint32_t)((grp & 1) * 16);
    const uint32_t aRow = (uint32_t)((wm * 64 + (grp & 1) * 8 + lr) * 128);
    const uint32_t bRow = (uint32_t)((wn * 32 + (grp >> 1) * 8 + lr) * 128);
    // base addresses into stage 0 (stage offset added as a constant per chunk)
    const uint32_t aBase = smem_base + aRow;
    const uint32_t bBase = smem_base + TILE_BYTES + bRow;

    float acc[4][4][4];
#pragma unroll
    for (int mi = 0; mi < 4; mi++)
#pragma unroll
        for (int ni = 0; ni < 4; ni++)
#pragma unroll
            for (int r = 0; r < 4; r++) acc[mi][ni][r] = 0.0f;

    // one k16 step: B frags first, then A[0]; interleave A[mi+1] with row-mi MMAs
#define KSTEP(stOfs, ks) do {                                                \
    uint32_t af[4][4], bf[2][4];                                             \
    const uint32_t _ca = ((uint32_t)((ks) * 32) + aHi) ^ xorv;               \
    const uint32_t _cb = ((uint32_t)((ks) * 32) + bHi) ^ xorv;               \
    ldsm4(bf[0], bBase + (stOfs) + _cb);                                     \
    ldsm4(bf[1], bBase + (stOfs) + 2048u + _cb);                             \
    ldsm4(af[0], aBase + (stOfs) + _ca);                                     \
    _Pragma("unroll")                                                        \
    for (int mi = 0; mi < 4; mi++) {                                         \
        if (mi < 3)                                                          \
            ldsm4(af[mi + 1], aBase + (stOfs) + (uint32_t)((mi + 1) * 2048) + _ca); \
        _Pragma("unroll")                                                    \
        for (int ni = 0; ni < 4; ni++) {                                     \
            const int nf = ni >> 1, p = (ni & 1) * 2;                        \
            mma_f16(acc[mi][ni], af[mi], bf[nf][p], bf[nf][p + 1]);          \
        }                                                                    \
    }                                                                        \
} while (0)

#define CHUNK_BODY(c) do {                                                   \
    const uint32_t _ofs = (uint32_t)(((c) % STAGES) * STAGE_BYTES);          \
    KSTEP(_ofs, 0); KSTEP(_ofs, 1); KSTEP(_ofs, 2); KSTEP(_ofs, 3);          \
} while (0)

    // ---- fully unrolled pipeline ----
    // chunk 0: 3 groups in flight, need group 0 -> wait<2>
    cp_wait<2>(); __syncthreads();
    CHUNK_BODY(0);
    __syncthreads(); ISSUE(3);

    cp_wait<2>(); __syncthreads();
    CHUNK_BODY(1);
    __syncthreads(); ISSUE(4);

    cp_wait<2>(); __syncthreads();
    CHUNK_BODY(2);
    __syncthreads(); ISSUE(5);

    cp_wait<2>(); __syncthreads();
    CHUNK_BODY(3);

    cp_wait<1>(); __syncthreads();
    CHUNK_BODY(4);

    cp_wait<0>(); __syncthreads();
    CHUNK_BODY(5);

    // ------------------------- epilogue -------------------------
    float scr[8], ccr[8], w2r[8];
#pragma unroll
    for (int ni = 0; ni < 4; ni++)
#pragma unroll
        for (int j = 0; j < 2; j++) {
            const int k = wn * 32 + ni * 8 + (lane & 3) * 2 + j;
            scr[ni * 2 + j] = sc_s[k];
            ccr[ni * 2 + j] = cc_s[k];
            w2r[ni * 2 + j] = w2_s[k];
        }

#pragma unroll
    for (int mi = 0; mi < 4; mi++) {
#pragma unroll
        for (int h = 0; h < 2; h++) {
            float s = 0.0f;
#pragma unroll
            for (int ni = 0; ni < 4; ni++) {
#pragma unroll
                for (int j = 0; j < 2; j++) {
                    float y = fmaf(acc[mi][ni][h * 2 + j],
                                   scr[ni * 2 + j], ccr[ni * 2 + j]);
                    y = fmaxf(y, 0.01f * y);          // LeakyReLU
                    s = fmaf(y, w2r[ni * 2 + j], s);
                }
            }
            s += __shfl_xor_sync(0xffffffffu, s, 1);
            s += __shfl_xor_sync(0xffffffffu, s, 2);
            if ((lane & 3) == 0) {
                const int row = wm * 64 + mi * 16 + h * 8 + (lane >> 2);
                red[row * 4 + wn] = s;
            }
        }
    }
    __syncthreads();

    if (tid < 128) {
        const float s = red[tid * 4 + 0] + red[tid * 4 + 1]
                      + red[tid * 4 + 2] + red[tid * 4 + 3] + b2[t];
        out[(size_t)(b0 + tid) * T_ + t] = s;
    }
#undef ISSUE
#undef KSTEP
#undef CHUNK_BODY
}

// ----------------------------------------------------------------------------
// launch
// ----------------------------------------------------------------------------
extern "C" void kernel_launch(void* const* d_in, const int* in_sizes, int n_in,
                              void* d_out, int out_size)
{
    const float* f     = (const float*)d_in[0];
    const float* W1    = (const float*)d_in[1];
    const float* b1    = (const float*)d_in[2];
    const float* gamma = (const float*)d_in[3];
    const float* beta  = (const float*)d_in[4];
    const float* rmean = (const float*)d_in[5];
    const float* rvar  = (const float*)d_in[6];
    const float* W2    = (const float*)d_in[7];
    const float* b2    = (const float*)d_in[8];
    float* out = (float*)d_out;

    {
        const size_t total4 = (size_t)NF / 4 + (size_t)NW / 4;
        const int blocks = (int)((total4 + 255) / 256);
        split_kernel<<<blocks, 256>>>(f, W1);
    }

    cudaFuncSetAttribute(heads_mma_kernel,
                         cudaFuncAttributeMaxDynamicSharedMemorySize, SMEM_TOTAL);
    dim3 grid(B_ / BM, T_);
    heads_mma_kernel<<<grid, 256, SMEM_TOTAL>>>(b1, gamma, beta, rmean, rvar,
                                                W2, b2, out);
}